// round 12
// baseline (speedup 1.0000x reference)
#include <cuda_runtime.h>
#include <math.h>
#include <math_constants.h>
#include <stdint.h>

#define BSZ  128
#define TLEN 500
#define ISZ  700
#define HSZ  256
#define OSZ  20
#define BJ0  0.01f

// Scratch. g_hpre layout: [b][t][n]
__device__ float    g_hpre[(size_t)BSZ * TLEN * HSZ];
__device__ float    g_wit[ISZ * HSZ];               // W_i2h^T [700][256]
__device__ float    g_wth[HSZ * HSZ];               // W_h2h^T [j][i]
__device__ unsigned g_ball[(size_t)BSZ * TLEN * 8]; // spike masks [b][t][8]
__device__ float    g_oin[(size_t)BSZ * TLEN * OSZ];
__device__ float    g_om [(size_t)BSZ * TLEN * OSZ];

// ---------------------------------------------------------------------------
__global__ void prep_kernel(const float* __restrict__ Wi,
                            const float* __restrict__ Wh) {
    int idx = blockIdx.x * blockDim.x + threadIdx.x;
    if (idx < ISZ * HSZ) {
        int k = idx / HSZ, n = idx % HSZ;
        g_wit[idx] = Wi[n * ISZ + k];
    }
    if (idx < HSZ * HSZ) {
        int j = idx / HSZ, i = idx % HSZ;
        g_wth[idx] = Wh[i * HSZ + j];
    }
}

// ---------------------------------------------------------------------------
// Persistent GEMM (R4 exact; bitwise-identical hpre)
// ---------------------------------------------------------------------------
#define FMA2(acc, a, b) \
    asm("fma.rn.f32x2 %0, %1, %2, %0;" : "+l"(acc) : "l"(a), "l"(b))

#define GEMM_TILES 1000
#define GEMM_GRID  296

__global__ void __launch_bounds__(256, 2) gemm_kernel(
    const float* __restrict__ A,
    const float* __restrict__ bi,
    const float* __restrict__ bh) {
    const int N = HSZ, K = ISZ;
    __shared__ __align__(16) float As[2][8][128];
    __shared__ __align__(16) float Bs[2][8][128];

    int tid = threadIdx.x;
    int tx = tid & 15, ty = tid >> 4;
    int arow  = tid >> 1,  acol4 = (tid & 1) * 4;
    int brow  = tid >> 5,  bcol4 = (tid & 31) * 4;

    for (int tile = blockIdx.x; tile < GEMM_TILES; tile += GEMM_GRID) {
        int bm = (tile >> 1) * 128;
        int bn = (tile & 1) * 128;
        const float* Aptr = A + (size_t)(bm + arow) * K;

        unsigned long long acc2[8][4];
#pragma unroll
        for (int i = 0; i < 8; i++)
#pragma unroll
            for (int j = 0; j < 4; j++) acc2[i][j] = 0ull;

        {
            float4 av = make_float4(0.f, 0.f, 0.f, 0.f);
            float4 bv = make_float4(0.f, 0.f, 0.f, 0.f);
            if (acol4 < K) av = *(const float4*)(Aptr + acol4);
            if (brow  < K) bv = *(const float4*)(g_wit + (size_t)brow * N + bn + bcol4);
            As[0][acol4 + 0][arow] = av.x;
            As[0][acol4 + 1][arow] = av.y;
            As[0][acol4 + 2][arow] = av.z;
            As[0][acol4 + 3][arow] = av.w;
            *(float4*)&Bs[0][brow][bcol4] = bv;
        }
        __syncthreads();

        int p = 0;
        for (int k0 = 0; k0 < K; k0 += 8) {
            bool more = (k0 + 8) < K;
            float4 av2 = make_float4(0.f, 0.f, 0.f, 0.f);
            float4 bv2 = make_float4(0.f, 0.f, 0.f, 0.f);
            if (more) {
                int ac = k0 + 8 + acol4;
                int bk = k0 + 8 + brow;
                if (ac < K) av2 = *(const float4*)(Aptr + ac);
                if (bk < K) bv2 = *(const float4*)(g_wit + (size_t)bk * N + bn + bcol4);
            }
#pragma unroll
            for (int kk = 0; kk < 8; kk++) {
                float4 a0 = *(const float4*)&As[p][kk][ty * 8];
                float4 a1 = *(const float4*)&As[p][kk][ty * 8 + 4];
                const unsigned long long* bp =
                    (const unsigned long long*)&Bs[p][kk][tx * 8];
                unsigned long long bb0 = bp[0], bb1 = bp[1], bb2 = bp[2], bb3 = bp[3];
                float af[8] = {a0.x, a0.y, a0.z, a0.w, a1.x, a1.y, a1.z, a1.w};
#pragma unroll
                for (int i = 0; i < 8; i++) {
                    unsigned long long aa;
                    unsigned ai = __float_as_uint(af[i]);
                    asm("mov.b64 %0, {%1, %1};" : "=l"(aa) : "r"(ai));
                    FMA2(acc2[i][0], aa, bb0);
                    FMA2(acc2[i][1], aa, bb1);
                    FMA2(acc2[i][2], aa, bb2);
                    FMA2(acc2[i][3], aa, bb3);
                }
            }
            if (more) {
                As[p ^ 1][acol4 + 0][arow] = av2.x;
                As[p ^ 1][acol4 + 1][arow] = av2.y;
                As[p ^ 1][acol4 + 2][arow] = av2.z;
                As[p ^ 1][acol4 + 3][arow] = av2.w;
                *(float4*)&Bs[p ^ 1][brow][bcol4] = bv2;
            }
            __syncthreads();
            p ^= 1;
        }

        float biasv[8];
#pragma unroll
        for (int j = 0; j < 8; j++) {
            int n = bn + tx * 8 + j;
            biasv[j] = bi[n] + bh[n];
        }
#pragma unroll
        for (int i = 0; i < 8; i++) {
            size_t m = (size_t)(bm + ty * 8 + i);
            float r[8];
#pragma unroll
            for (int j = 0; j < 4; j++) {
                unsigned lo, hi;
                asm("mov.b64 {%0, %1}, %2;" : "=r"(lo), "=r"(hi) : "l"(acc2[i][j]));
                r[2 * j]     = __uint_as_float(lo) + biasv[2 * j];
                r[2 * j + 1] = __uint_as_float(hi) + biasv[2 * j + 1];
            }
            float4 v0 = make_float4(r[0], r[1], r[2], r[3]);
            float4 v1 = make_float4(r[4], r[5], r[6], r[7]);
            *(float4*)(g_hpre + m * HSZ + bn + tx * 8)     = v0;
            *(float4*)(g_hpre + m * HSZ + bn + tx * 8 + 4) = v1;
        }
    }
}

// ---------------------------------------------------------------------------
// Shared helpers
// ---------------------------------------------------------------------------
__device__ __forceinline__ uint32_t smem_u32(const void* p) {
    uint32_t a;
    asm("{ .reg .u64 t; cvta.to.shared.u64 t, %1; cvt.u32.u64 %0, t; }"
        : "=r"(a) : "l"(p));
    return a;
}

__device__ __forceinline__ void st_smem_u64(uint32_t addr,
                                            unsigned long long v) {
    asm volatile("st.volatile.shared.b64 [%0], %1;" :: "r"(addr), "l"(v)
                 : "memory");
}

__device__ __forceinline__ void st_peer_u64(uint32_t local_addr, uint32_t rank,
                                            unsigned long long v) {
    asm volatile(
        "{.reg .b32 ra; mapa.shared::cluster.u32 ra, %0, %1;"
        " st.shared::cluster.b64 [ra], %2;}"
        :: "r"(local_addr), "r"(rank), "l"(v) : "memory");
}

__device__ __forceinline__ unsigned long long ld_smem_u64_vol(uint32_t addr) {
    unsigned long long v;
    asm volatile("ld.volatile.shared.b64 %0, [%1];" : "=l"(v) : "r"(addr)
                 : "memory");
    return v;
}

#define TREE8(w0,w1,w2,w3,w4,w5,w6,w7) \
    (((w0 + w1) + (w2 + w3)) + ((w4 + w5) + (w6 + w7)))

// Warp-private scatter: ascending index list of set bits in w[0..7].
__device__ __forceinline__ int warp_scatter8(const unsigned w[8], int lane,
                                             int* __restrict__ seg) {
    int cnt = 0;
#pragma unroll
    for (int k2 = 0; k2 < 8; k2++) cnt += __popc(w[k2]);
    const int wi = lane >> 2;
    const int bitbase = (lane & 3) * 8;
    int pos = 0;
#pragma unroll
    for (int k2 = 0; k2 < 8; k2++)
        if (k2 < wi) pos += __popc(w[k2]);
    unsigned myw = w[wi];
    pos += __popc(myw & ((1u << bitbase) - 1u));
    unsigned byte = (myw >> bitbase) & 0xffu;
    int base_n = lane * 8;
#pragma unroll
    for (int k2 = 0; k2 < 8; k2++)
        if (byte & (1u << k2)) seg[pos++] = base_n + k2;
    __syncwarp();
    return cnt;
}

// 16-wide gather: same add ORDER as 8-wide (racc+=T1; racc+=T2).
__device__ __forceinline__ float gather_list16(const float* __restrict__ w,
                                               const int* __restrict__ lst,
                                               int cnt, int stride) {
    float racc = 0.f;
    int i = 0;
#pragma unroll 1
    for (; i + 16 <= cnt; i += 16) {
        int4 ja = *(const int4*)(lst + i);
        int4 jb = *(const int4*)(lst + i + 4);
        int4 jc = *(const int4*)(lst + i + 8);
        int4 jd = *(const int4*)(lst + i + 12);
        float w0 = w[ja.x * stride], w1 = w[ja.y * stride];
        float w2 = w[ja.z * stride], w3 = w[ja.w * stride];
        float w4 = w[jb.x * stride], w5 = w[jb.y * stride];
        float w6 = w[jb.z * stride], w7 = w[jb.w * stride];
        float x0 = w[jc.x * stride], x1 = w[jc.y * stride];
        float x2 = w[jc.z * stride], x3 = w[jc.w * stride];
        float x4 = w[jd.x * stride], x5 = w[jd.y * stride];
        float x6 = w[jd.z * stride], x7 = w[jd.w * stride];
        float t1 = TREE8(w0, w1, w2, w3, w4, w5, w6, w7);
        float t2 = TREE8(x0, x1, x2, x3, x4, x5, x6, x7);
        racc += t1;
        racc += t2;
    }
    if (i + 8 <= cnt) {
        int4 ja = *(const int4*)(lst + i);
        int4 jb = *(const int4*)(lst + i + 4);
        float w0 = w[ja.x * stride], w1 = w[ja.y * stride];
        float w2 = w[ja.z * stride], w3 = w[ja.w * stride];
        float w4 = w[jb.x * stride], w5 = w[jb.y * stride];
        float w6 = w[jb.z * stride], w7 = w[jb.w * stride];
        racc += TREE8(w0, w1, w2, w3, w4, w5, w6, w7);
        i += 8;
    }
#pragma unroll 1
    for (; i < cnt; ++i)
        racc += w[lst[i] * stride];
    return racc;
}

// ---------------------------------------------------------------------------
// Scan: cluster of 2 CTAs per batch pair, 256 threads = 8 hidden warps.
// Sync = self-flagging tagged ballots: u64 {tag=t+1, ballot} written once
// locally + once to the peer; consumers spin on their own smem (lane<8 each
// polls one word, __all_sync). No mbarrier, no fence, 2-slot ring
// (self-synchronizing: producer advance implies all readers done).
// ---------------------------------------------------------------------------
#define NTH 256
#define SCAN_SMEM_FLOATS 35400   // 141,600 bytes

__global__ void __launch_bounds__(NTH, 1) __cluster_dims__(2, 1, 1)
scan_kernel(const float* __restrict__ tau_m_h,
            const float* __restrict__ h0)
{
    extern __shared__ float smf[];
    float*    s_wt   = smf;                        // [256][128] 128 KB
    float*    s_spk0 = smf + 32768;                // [2][256]
    int*      s_idx  = (int*)(smf + 33280);        // [8 warps][256]
    unsigned long long* s_tag =
        (unsigned long long*)(smf + 35328);        // [2 slot][2 batch][8] u64

    const int tid  = threadIdx.x;
    const int lane = tid & 31;
    const int wid  = tid >> 5;
    const int r    = blockIdx.x & 1;
    const int b0   = blockIdx.x & ~1;

    for (int i = tid; i < 8192; i += NTH) {
        int j = i >> 5, c = i & 31;
        ((float4*)s_wt)[i] =
            *(const float4*)(g_wth + (size_t)j * HSZ + r * 128 + c * 4);
    }
    for (int i = tid; i < 2 * HSZ; i += NTH) {
        int bl2 = i >> 8, j = i & 255;
        s_spk0[i] = h0[(size_t)(b0 + bl2) * HSZ + j];
    }
    if (tid < 32) s_tag[tid] = 0ull;

    const int bl = (tid >> 7) & 1;
    const int il = tid & 127;
    const int q  = (wid & 3);
    const int col = r * 128 + il;
    const int gw  = r * 4 + q;                     // my global ballot word
    int* myseg = s_idx + wid * 256;

    const float a_h      = expf(-1.f / tau_m_h[col]);
    const float one_m_ah = 1.f - a_h;
    float h_mem = h0[(size_t)(b0 + bl) * HSZ + col];
    float spf   = h_mem;

    __syncthreads();
    asm volatile("barrier.cluster.arrive.aligned;" ::: "memory");
    asm volatile("barrier.cluster.wait.aligned;" ::: "memory");

    const uint32_t tag_base = smem_u32(s_tag);
    // my producer word address (slot selected per step)
    const uint32_t my_off   = (uint32_t)(bl * 8 + gw) * 8u;
    // my poll word address (lane < 8): word (bl*8 + lane)
    const uint32_t poll_off = (uint32_t)(bl * 8 + (lane & 7)) * 8u;

    const float* hp = g_hpre + ((size_t)(b0 + bl) * TLEN) * HSZ + col;
    const float* wcol = s_wt + il;
    float pre = __ldcs(hp);
    unsigned* gb = g_ball + ((size_t)(b0 + bl) * TLEN) * 8 + gw;

#pragma unroll 1
    for (int t = 0; t < TLEN; ++t) {
        int cnt = 0;
        if (t >= 1) {
            // ---- spin on my own smem for 8 tagged ballots (tag == t) ----
            const uint32_t pa = tag_base + (uint32_t)(((t - 1) & 1) * 128) + poll_off;
            const bool need = (lane < 8);
            unsigned myball = 0;
            for (;;) {
                unsigned long long v = need ? ld_smem_u64_vol(pa) : 0ull;
                bool ok = !need || ((unsigned)(v >> 32) == (unsigned)t);
                if (__all_sync(0xffffffffu, ok)) {
                    myball = (unsigned)v;
                    break;
                }
            }
            unsigned w[8];
#pragma unroll
            for (int k2 = 0; k2 < 8; k2++)
                w[k2] = __shfl_sync(0xffffffffu, myball, k2);
            cnt = warp_scatter8(w, lane, myseg);
        }

        float acc = pre;
        if (t + 1 < TLEN) pre = __ldcs(hp + (size_t)(t + 1) * HSZ);

        float racc;
        if (t == 0) {
            const float* sp0 = s_spk0 + bl * HSZ;
            racc = 0.f;
#pragma unroll 8
            for (int j = 0; j < HSZ; ++j)
                racc += wcol[j * 128] * sp0[j];
        } else {
            racc = gather_list16(wcol, myseg, cnt, 128);
        }
        acc += racc;

        h_mem = h_mem * a_h + one_m_ah * acc - BJ0 * spf;
        int sp = (h_mem - BJ0) > 0.f;
        spf = sp ? 1.f : 0.f;
        unsigned bal = __ballot_sync(0xffffffffu, sp);
        if (lane == 0) {
            unsigned long long pk =
                (unsigned long long)bal |
                ((unsigned long long)(unsigned)(t + 1) << 32);
            uint32_t sa = tag_base + (uint32_t)((t & 1) * 128) + my_off;
            st_smem_u64(sa, pk);                       // local consumers
            st_peer_u64(sa, (unsigned)(r ^ 1), pk);    // peer consumers
            __stcs(gb + (size_t)t * 8, bal);           // output post-pass
        }
    }

    asm volatile("barrier.cluster.arrive.aligned;" ::: "memory");
    asm volatile("barrier.cluster.wait.aligned;" ::: "memory");
}

// ---------------------------------------------------------------------------
// Post-pass A: oin[b][t][o] = sum over spiking j of Wo^T[j][o]
// ---------------------------------------------------------------------------
__global__ void __launch_bounds__(128) oin_kernel(const float* __restrict__ Wo) {
    __shared__ float s_woT[HSZ * OSZ];     // [j][o], 20 KB
    __shared__ int   s_list[4][256];

    int tid = threadIdx.x, lane = tid & 31, wid = tid >> 5;
    for (int i = tid; i < OSZ * HSZ; i += 128) {
        int o = i >> 8, j = i & 255;
        s_woT[j * OSZ + o] = Wo[i];
    }
    __syncthreads();

    int task = blockIdx.x * 4 + wid;       // = b*TLEN + t, < 64000
    const unsigned* gb = g_ball + (size_t)task * 8;
    unsigned w[8];
#pragma unroll
    for (int k = 0; k < 8; k++) w[k] = gb[k];
    int cnt = warp_scatter8(w, lane, s_list[wid]);
    if (lane < OSZ) {
        float v = gather_list16(s_woT + lane, s_list[wid], cnt, OSZ);
        g_oin[(size_t)task * OSZ + lane] = v;
    }
}

// ---------------------------------------------------------------------------
// Post-pass B: per-(b,o) ALIF recurrence over t (2560 threads)
// ---------------------------------------------------------------------------
__global__ void __launch_bounds__(256) orec_kernel(
    const float* __restrict__ bo_bias,
    const float* __restrict__ tau_adp_o,
    const float* __restrict__ tau_m_o,
    const float* __restrict__ o0) {
    int gt = blockIdx.x * blockDim.x + threadIdx.x;
    if (gt >= BSZ * OSZ) return;
    int b = gt / OSZ, o = gt % OSZ;

    const float alpha = expf(-1.f / tau_m_o[o]);
    const float ro    = expf(-1.f / tau_adp_o[o]);
    const float oma   = 1.f - alpha;
    const float omr   = 1.f - ro;
    const float bias  = bo_bias[o];

    float om  = o0[(size_t)b * OSZ + o];
    float osp = om;
    float bo  = BJ0;

    const float* oi = g_oin + (size_t)b * TLEN * OSZ + o;
    float*       od = g_om  + (size_t)b * TLEN * OSZ + o;
    float pre = oi[0];
#pragma unroll 1
    for (int t = 0; t < TLEN; ++t) {
        float oin = bias + pre;
        if (t + 1 < TLEN) pre = oi[(size_t)(t + 1) * OSZ];
        bo = ro * bo + omr * osp;
        float Bo = BJ0 + 1.8f * bo;
        om = om * alpha + oma * oin - Bo * osp;
        osp = ((om - Bo) > 0.f) ? 1.f : 0.f;
        od[(size_t)t * OSZ] = om;
    }
}

// ---------------------------------------------------------------------------
// Post-pass C: log-softmax per (b,t), one warp each
// ---------------------------------------------------------------------------
__global__ void __launch_bounds__(256) softmax_kernel(float* __restrict__ out) {
    int lane = threadIdx.x & 31, wid = threadIdx.x >> 5;
    int task = blockIdx.x * 8 + wid;       // = b*TLEN + t
    int b = task / TLEN, t = task % TLEN;

    float om = (lane < OSZ) ? g_om[(size_t)task * OSZ + lane] : -CUDART_INF_F;
    float mx = om;
#pragma unroll
    for (int off = 16; off; off >>= 1)
        mx = fmaxf(mx, __shfl_xor_sync(0xffffffffu, mx, off));
    float e = (lane < OSZ) ? __expf(om - mx) : 0.f;
    float s = e;
#pragma unroll
    for (int off = 16; off; off >>= 1)
        s += __shfl_xor_sync(0xffffffffu, s, off);
    if (lane < OSZ)
        out[((size_t)b * OSZ + lane) * TLEN + t] = om - mx - __logf(s);
}

// ---------------------------------------------------------------------------
extern "C" void kernel_launch(void* const* d_in, const int* in_sizes, int n_in,
                              void* d_out, int out_size) {
    const float* x         = (const float*)d_in[0];
    const float* W_i2h     = (const float*)d_in[1];
    const float* b_i2h     = (const float*)d_in[2];
    const float* W_h2h     = (const float*)d_in[3];
    const float* b_h2h     = (const float*)d_in[4];
    const float* W_h2o     = (const float*)d_in[5];
    const float* b_h2o     = (const float*)d_in[6];
    const float* tau_adp_o = (const float*)d_in[8];
    const float* tau_m_h   = (const float*)d_in[9];
    const float* tau_m_o   = (const float*)d_in[10];
    const float* h0        = (const float*)d_in[11];
    const float* o0        = (const float*)d_in[12];
    float* out = (float*)d_out;

    static int inited = 0;
    if (!inited) {
        cudaFuncSetAttribute(scan_kernel,
                             cudaFuncAttributeMaxDynamicSharedMemorySize,
                             SCAN_SMEM_FLOATS * 4);
        inited = 1;
    }

    prep_kernel<<<(ISZ * HSZ + 255) / 256, 256>>>(W_i2h, W_h2h);

    gemm_kernel<<<GEMM_GRID, 256>>>(x, b_i2h, b_h2h);

    scan_kernel<<<BSZ, NTH, SCAN_SMEM_FLOATS * 4>>>(tau_m_h, h0);

    oin_kernel<<<BSZ * TLEN / 4, 128>>>(W_h2o);

    orec_kernel<<<(BSZ * OSZ + 255) / 256, 256>>>(b_h2o, tau_adp_o, tau_m_o, o0);

    softmax_kernel<<<BSZ * TLEN / 8, 256>>>(out);
}

// round 13
// speedup vs baseline: 1.3669x; 1.3669x over previous
#include <cuda_runtime.h>
#include <math.h>
#include <math_constants.h>
#include <stdint.h>

#define BSZ  128
#define TLEN 500
#define ISZ  700
#define HSZ  256
#define OSZ  20
#define BJ0  0.01f

// Scratch. g_hpre layout: [b][t][n]
__device__ float    g_hpre[(size_t)BSZ * TLEN * HSZ];
__device__ float    g_wit[ISZ * HSZ];               // W_i2h^T [700][256]
__device__ float    g_wth[HSZ * HSZ];               // W_h2h^T [j][i]
__device__ unsigned g_ball[(size_t)BSZ * TLEN * 8]; // spike masks [b][t][8]
__device__ float    g_oin[(size_t)BSZ * TLEN * OSZ];
__device__ float    g_om [(size_t)BSZ * TLEN * OSZ];

// ---------------------------------------------------------------------------
__global__ void prep_kernel(const float* __restrict__ Wi,
                            const float* __restrict__ Wh) {
    int idx = blockIdx.x * blockDim.x + threadIdx.x;
    if (idx < ISZ * HSZ) {
        int k = idx / HSZ, n = idx % HSZ;
        g_wit[idx] = Wi[n * ISZ + k];
    }
    if (idx < HSZ * HSZ) {
        int j = idx / HSZ, i = idx % HSZ;
        g_wth[idx] = Wh[i * HSZ + j];
    }
}

// ---------------------------------------------------------------------------
// Persistent GEMM (R4 exact; bitwise-identical hpre)
// ---------------------------------------------------------------------------
#define FMA2(acc, a, b) \
    asm("fma.rn.f32x2 %0, %1, %2, %0;" : "+l"(acc) : "l"(a), "l"(b))

#define GEMM_TILES 1000
#define GEMM_GRID  296

__global__ void __launch_bounds__(256, 2) gemm_kernel(
    const float* __restrict__ A,
    const float* __restrict__ bi,
    const float* __restrict__ bh) {
    const int N = HSZ, K = ISZ;
    __shared__ __align__(16) float As[2][8][128];
    __shared__ __align__(16) float Bs[2][8][128];

    int tid = threadIdx.x;
    int tx = tid & 15, ty = tid >> 4;
    int arow  = tid >> 1,  acol4 = (tid & 1) * 4;
    int brow  = tid >> 5,  bcol4 = (tid & 31) * 4;

    for (int tile = blockIdx.x; tile < GEMM_TILES; tile += GEMM_GRID) {
        int bm = (tile >> 1) * 128;
        int bn = (tile & 1) * 128;
        const float* Aptr = A + (size_t)(bm + arow) * K;

        unsigned long long acc2[8][4];
#pragma unroll
        for (int i = 0; i < 8; i++)
#pragma unroll
            for (int j = 0; j < 4; j++) acc2[i][j] = 0ull;

        {
            float4 av = make_float4(0.f, 0.f, 0.f, 0.f);
            float4 bv = make_float4(0.f, 0.f, 0.f, 0.f);
            if (acol4 < K) av = *(const float4*)(Aptr + acol4);
            if (brow  < K) bv = *(const float4*)(g_wit + (size_t)brow * N + bn + bcol4);
            As[0][acol4 + 0][arow] = av.x;
            As[0][acol4 + 1][arow] = av.y;
            As[0][acol4 + 2][arow] = av.z;
            As[0][acol4 + 3][arow] = av.w;
            *(float4*)&Bs[0][brow][bcol4] = bv;
        }
        __syncthreads();

        int p = 0;
        for (int k0 = 0; k0 < K; k0 += 8) {
            bool more = (k0 + 8) < K;
            float4 av2 = make_float4(0.f, 0.f, 0.f, 0.f);
            float4 bv2 = make_float4(0.f, 0.f, 0.f, 0.f);
            if (more) {
                int ac = k0 + 8 + acol4;
                int bk = k0 + 8 + brow;
                if (ac < K) av2 = *(const float4*)(Aptr + ac);
                if (bk < K) bv2 = *(const float4*)(g_wit + (size_t)bk * N + bn + bcol4);
            }
#pragma unroll
            for (int kk = 0; kk < 8; kk++) {
                float4 a0 = *(const float4*)&As[p][kk][ty * 8];
                float4 a1 = *(const float4*)&As[p][kk][ty * 8 + 4];
                const unsigned long long* bp =
                    (const unsigned long long*)&Bs[p][kk][tx * 8];
                unsigned long long bb0 = bp[0], bb1 = bp[1], bb2 = bp[2], bb3 = bp[3];
                float af[8] = {a0.x, a0.y, a0.z, a0.w, a1.x, a1.y, a1.z, a1.w};
#pragma unroll
                for (int i = 0; i < 8; i++) {
                    unsigned long long aa;
                    unsigned ai = __float_as_uint(af[i]);
                    asm("mov.b64 %0, {%1, %1};" : "=l"(aa) : "r"(ai));
                    FMA2(acc2[i][0], aa, bb0);
                    FMA2(acc2[i][1], aa, bb1);
                    FMA2(acc2[i][2], aa, bb2);
                    FMA2(acc2[i][3], aa, bb3);
                }
            }
            if (more) {
                As[p ^ 1][acol4 + 0][arow] = av2.x;
                As[p ^ 1][acol4 + 1][arow] = av2.y;
                As[p ^ 1][acol4 + 2][arow] = av2.z;
                As[p ^ 1][acol4 + 3][arow] = av2.w;
                *(float4*)&Bs[p ^ 1][brow][bcol4] = bv2;
            }
            __syncthreads();
            p ^= 1;
        }

        float biasv[8];
#pragma unroll
        for (int j = 0; j < 8; j++) {
            int n = bn + tx * 8 + j;
            biasv[j] = bi[n] + bh[n];
        }
#pragma unroll
        for (int i = 0; i < 8; i++) {
            size_t m = (size_t)(bm + ty * 8 + i);
            float r[8];
#pragma unroll
            for (int j = 0; j < 4; j++) {
                unsigned lo, hi;
                asm("mov.b64 {%0, %1}, %2;" : "=r"(lo), "=r"(hi) : "l"(acc2[i][j]));
                r[2 * j]     = __uint_as_float(lo) + biasv[2 * j];
                r[2 * j + 1] = __uint_as_float(hi) + biasv[2 * j + 1];
            }
            float4 v0 = make_float4(r[0], r[1], r[2], r[3]);
            float4 v1 = make_float4(r[4], r[5], r[6], r[7]);
            *(float4*)(g_hpre + m * HSZ + bn + tx * 8)     = v0;
            *(float4*)(g_hpre + m * HSZ + bn + tx * 8 + 4) = v1;
        }
    }
}

// ---------------------------------------------------------------------------
// Shared helpers
// ---------------------------------------------------------------------------
__device__ __forceinline__ void st_peer_u32(uint32_t local_addr, uint32_t rank,
                                            uint32_t val) {
    asm volatile(
        "{.reg .b32 ra; mapa.shared::cluster.u32 ra, %0, %1;"
        " st.shared::cluster.b32 [ra], %2;}"
        :: "r"(local_addr), "r"(rank), "r"(val) : "memory");
}

__device__ __forceinline__ void mbar_arrive_local(uint32_t mbar) {
    asm volatile("mbarrier.arrive.release.cta.shared::cta.b64 _, [%0];"
                 :: "r"(mbar) : "memory");
}

__device__ __forceinline__ void mbar_arrive_peer(uint32_t mbar, uint32_t rank) {
    asm volatile(
        "{.reg .b32 ra; mapa.shared::cluster.u32 ra, %0, %1;"
        " mbarrier.arrive.release.cluster.shared::cluster.b64 _, [ra];}"
        :: "r"(mbar), "r"(rank) : "memory");
}

__device__ __forceinline__ void mbar_wait_parity(uint32_t mbar, uint32_t parity) {
    uint32_t done;
    asm volatile(
        "{\n\t.reg .pred p;\n\t"
        "mbarrier.try_wait.parity.acquire.cluster.shared::cta.b64 p, [%1], %2;\n\t"
        "selp.b32 %0, 1, 0, p;\n\t}"
        : "=r"(done) : "r"(mbar), "r"(parity) : "memory");
    if (!done) {
        asm volatile(
            "{\n\t.reg .pred P1;\n\t"
            "WL_%=:\n\t"
            "mbarrier.try_wait.parity.acquire.cluster.shared::cta.b64 P1, [%0], %1, 0x989680;\n\t"
            "@P1 bra.uni WD_%=;\n\t"
            "bra.uni WL_%=;\n\t"
            "WD_%=:\n\t}"
            :: "r"(mbar), "r"(parity) : "memory");
    }
}

__device__ __forceinline__ uint32_t smem_u32(const void* p) {
    uint32_t a;
    asm("{ .reg .u64 t; cvta.to.shared.u64 t, %1; cvt.u32.u64 %0, t; }"
        : "=r"(a) : "l"(p));
    return a;
}

#define TREE8(w0,w1,w2,w3,w4,w5,w6,w7) \
    (((w0 + w1) + (w2 + w3)) + ((w4 + w5) + (w6 + w7)))

// Warp-private scatter: ascending index list of set bits in w[0..7].
__device__ __forceinline__ int warp_scatter8(const unsigned w[8], int lane,
                                             int* __restrict__ seg) {
    int cnt = 0;
#pragma unroll
    for (int k2 = 0; k2 < 8; k2++) cnt += __popc(w[k2]);
    const int wi = lane >> 2;
    const int bitbase = (lane & 3) * 8;
    int pos = 0;
#pragma unroll
    for (int k2 = 0; k2 < 8; k2++)
        if (k2 < wi) pos += __popc(w[k2]);
    unsigned myw = w[wi];
    pos += __popc(myw & ((1u << bitbase) - 1u));
    unsigned byte = (myw >> bitbase) & 0xffu;
    int base_n = lane * 8;
#pragma unroll
    for (int k2 = 0; k2 < 8; k2++)
        if (byte & (1u << k2)) seg[pos++] = base_n + k2;
    __syncwarp();
    return cnt;
}

// 16-wide gather: same add ORDER as 8-wide (racc+=T1; racc+=T2).
__device__ __forceinline__ float gather_list16(const float* __restrict__ w,
                                               const int* __restrict__ lst,
                                               int cnt, int stride) {
    float racc = 0.f;
    int i = 0;
#pragma unroll 1
    for (; i + 16 <= cnt; i += 16) {
        int4 ja = *(const int4*)(lst + i);
        int4 jb = *(const int4*)(lst + i + 4);
        int4 jc = *(const int4*)(lst + i + 8);
        int4 jd = *(const int4*)(lst + i + 12);
        float w0 = w[ja.x * stride], w1 = w[ja.y * stride];
        float w2 = w[ja.z * stride], w3 = w[ja.w * stride];
        float w4 = w[jb.x * stride], w5 = w[jb.y * stride];
        float w6 = w[jb.z * stride], w7 = w[jb.w * stride];
        float x0 = w[jc.x * stride], x1 = w[jc.y * stride];
        float x2 = w[jc.z * stride], x3 = w[jc.w * stride];
        float x4 = w[jd.x * stride], x5 = w[jd.y * stride];
        float x6 = w[jd.z * stride], x7 = w[jd.w * stride];
        float t1 = TREE8(w0, w1, w2, w3, w4, w5, w6, w7);
        float t2 = TREE8(x0, x1, x2, x3, x4, x5, x6, x7);
        racc += t1;
        racc += t2;
    }
    if (i + 8 <= cnt) {
        int4 ja = *(const int4*)(lst + i);
        int4 jb = *(const int4*)(lst + i + 4);
        float w0 = w[ja.x * stride], w1 = w[ja.y * stride];
        float w2 = w[ja.z * stride], w3 = w[ja.w * stride];
        float w4 = w[jb.x * stride], w5 = w[jb.y * stride];
        float w6 = w[jb.z * stride], w7 = w[jb.w * stride];
        racc += TREE8(w0, w1, w2, w3, w4, w5, w6, w7);
        i += 8;
    }
#pragma unroll 1
    for (; i < cnt; ++i)
        racc += w[lst[i] * stride];
    return racc;
}

// ---------------------------------------------------------------------------
// Scan: cluster of 2 CTAs per batch pair, 256 threads = 8 hidden warps.
// TWO per-batch mbarriers (count 8 = 4 local + 4 peer warp arrivals):
// the two batch lanes are fully decoupled; step waits on 8 warps, not 16.
// ---------------------------------------------------------------------------
#define NTH 256
#define SCAN_SMEM_FLOATS 35372   // 141,488 bytes

__global__ void __launch_bounds__(NTH, 1) __cluster_dims__(2, 1, 1)
scan_kernel(const float* __restrict__ tau_m_h,
            const float* __restrict__ h0)
{
    extern __shared__ float smf[];
    float*    s_wt   = smf;                        // [256][128] 128 KB
    float*    s_spk0 = smf + 32768;                // [2][256]
    int*      s_idx  = (int*)(smf + 33280);        // [8 warps][256]
    unsigned* s_bal  = (unsigned*)(smf + 35328);   // [2 par][2 batch][8]
    unsigned long long* s_mbar =
        (unsigned long long*)(smf + 35360);        // [2 batch]

    const int tid  = threadIdx.x;
    const int lane = tid & 31;
    const int wid  = tid >> 5;
    const int r    = blockIdx.x & 1;
    const int b0   = blockIdx.x & ~1;

    for (int i = tid; i < 8192; i += NTH) {
        int j = i >> 5, c = i & 31;
        ((float4*)s_wt)[i] =
            *(const float4*)(g_wth + (size_t)j * HSZ + r * 128 + c * 4);
    }
    for (int i = tid; i < 2 * HSZ; i += NTH) {
        int bl2 = i >> 8, j = i & 255;
        s_spk0[i] = h0[(size_t)(b0 + bl2) * HSZ + j];
    }
    if (tid < 2) {
        asm volatile("mbarrier.init.shared.b64 [%0], %1;"
                     :: "r"(smem_u32(s_mbar + tid)), "r"(8u) : "memory");
    }

    const int bl = (tid >> 7) & 1;
    const int il = tid & 127;
    const int q  = (wid & 3);
    const int col = r * 128 + il;
    const int gw  = r * 4 + q;
    int* myseg = s_idx + wid * 256;

    const float a_h      = expf(-1.f / tau_m_h[col]);
    const float one_m_ah = 1.f - a_h;
    float h_mem = h0[(size_t)(b0 + bl) * HSZ + col];
    float spf   = h_mem;

    __syncthreads();
    asm volatile("barrier.cluster.arrive.aligned;" ::: "memory");
    asm volatile("barrier.cluster.wait.aligned;" ::: "memory");

    const uint32_t bal_base = smem_u32(s_bal);
    const uint32_t mbar_u32 = smem_u32(s_mbar + bl);

    const float* hp = g_hpre + ((size_t)(b0 + bl) * TLEN) * HSZ + col;
    const float* wcol = s_wt + il;
    float pre = __ldcs(hp);
    unsigned* gb = g_ball + ((size_t)(b0 + bl) * TLEN) * 8 + gw;

#pragma unroll 1
    for (int t = 0; t < TLEN; ++t) {
        int cnt = 0;
        if (t >= 1) {
            mbar_wait_parity(mbar_u32, (t - 1) & 1);
            const unsigned* wp = s_bal + ((t - 1) & 1) * 16 + bl * 8;
            unsigned w[8];
#pragma unroll
            for (int k2 = 0; k2 < 8; k2++) w[k2] = wp[k2];
            cnt = warp_scatter8(w, lane, myseg);
        }

        float acc = pre;
        if (t + 1 < TLEN) pre = __ldcs(hp + (size_t)(t + 1) * HSZ);

        float racc;
        if (t == 0) {
            const float* sp0 = s_spk0 + bl * HSZ;
            racc = 0.f;
#pragma unroll 8
            for (int j = 0; j < HSZ; ++j)
                racc += wcol[j * 128] * sp0[j];
        } else {
            racc = gather_list16(wcol, myseg, cnt, 128);
        }
        acc += racc;

        h_mem = h_mem * a_h + one_m_ah * acc - BJ0 * spf;
        int sp = (h_mem - BJ0) > 0.f;
        spf = sp ? 1.f : 0.f;
        unsigned bal = __ballot_sync(0xffffffffu, sp);
        if (lane == 0) {
            int off = (t & 1) * 16 + bl * 8 + gw;
            s_bal[off] = bal;
            st_peer_u32(bal_base + off * 4, (unsigned)(r ^ 1), bal);
            mbar_arrive_local(mbar_u32);
            mbar_arrive_peer(mbar_u32, (unsigned)(r ^ 1));
            __stcs(gb + (size_t)t * 8, bal);   // for the output post-pass
        }
    }

    asm volatile("barrier.cluster.arrive.aligned;" ::: "memory");
    asm volatile("barrier.cluster.wait.aligned;" ::: "memory");
}

// ---------------------------------------------------------------------------
// Post-pass A (persistent): oin[b][t][o] = sum over spiking j of Wo^T[j][o].
// 500 blocks x 8 warps x 16 tasks: Wo^T smem fill paid once per block.
// Per-task arithmetic identical to R11 -> bitwise-identical oin.
// ---------------------------------------------------------------------------
#define OIN_WARPS 8
#define OIN_TASKS 16   // per warp

__global__ void __launch_bounds__(OIN_WARPS * 32) oin_kernel(
    const float* __restrict__ Wo) {
    __shared__ float s_woT[HSZ * OSZ];     // [j][o], 20 KB
    __shared__ int   s_list[OIN_WARPS][256];

    int tid = threadIdx.x, lane = tid & 31, wid = tid >> 5;
    for (int i = tid; i < OSZ * HSZ; i += OIN_WARPS * 32) {
        int o = i >> 8, j = i & 255;
        s_woT[j * OSZ + o] = Wo[i];
    }
    __syncthreads();

    int task0 = (blockIdx.x * OIN_WARPS + wid) * OIN_TASKS;
#pragma unroll 1
    for (int it = 0; it < OIN_TASKS; ++it) {
        int task = task0 + it;             // = b*TLEN + t, < 64000
        const unsigned* gb = g_ball + (size_t)task * 8;
        unsigned w[8];
#pragma unroll
        for (int k = 0; k < 8; k++) w[k] = gb[k];
        int cnt = warp_scatter8(w, lane, s_list[wid]);
        if (lane < OSZ) {
            float v = gather_list16(s_woT + lane, s_list[wid], cnt, OSZ);
            g_oin[(size_t)task * OSZ + lane] = v;
        }
        __syncwarp();
    }
}

// ---------------------------------------------------------------------------
// Post-pass B: per-(b,o) ALIF recurrence over t (2560 threads)
// ---------------------------------------------------------------------------
__global__ void __launch_bounds__(256) orec_kernel(
    const float* __restrict__ bo_bias,
    const float* __restrict__ tau_adp_o,
    const float* __restrict__ tau_m_o,
    const float* __restrict__ o0) {
    int gt = blockIdx.x * blockDim.x + threadIdx.x;
    if (gt >= BSZ * OSZ) return;
    int b = gt / OSZ, o = gt % OSZ;

    const float alpha = expf(-1.f / tau_m_o[o]);
    const float ro    = expf(-1.f / tau_adp_o[o]);
    const float oma   = 1.f - alpha;
    const float omr   = 1.f - ro;
    const float bias  = bo_bias[o];

    float om  = o0[(size_t)b * OSZ + o];
    float osp = om;
    float bo  = BJ0;

    const float* oi = g_oin + (size_t)b * TLEN * OSZ + o;
    float*       od = g_om  + (size_t)b * TLEN * OSZ + o;
    float pre = oi[0];
#pragma unroll 1
    for (int t = 0; t < TLEN; ++t) {
        float oin = bias + pre;
        if (t + 1 < TLEN) pre = oi[(size_t)(t + 1) * OSZ];
        bo = ro * bo + omr * osp;
        float Bo = BJ0 + 1.8f * bo;
        om = om * alpha + oma * oin - Bo * osp;
        osp = ((om - Bo) > 0.f) ? 1.f : 0.f;
        od[(size_t)t * OSZ] = om;
    }
}

// ---------------------------------------------------------------------------
// Post-pass C: log-softmax per (b,t), one warp each
// ---------------------------------------------------------------------------
__global__ void __launch_bounds__(256) softmax_kernel(float* __restrict__ out) {
    int lane = threadIdx.x & 31, wid = threadIdx.x >> 5;
    int task = blockIdx.x * 8 + wid;       // = b*TLEN + t
    int b = task / TLEN, t = task % TLEN;

    float om = (lane < OSZ) ? g_om[(size_t)task * OSZ + lane] : -CUDART_INF_F;
    float mx = om;
#pragma unroll
    for (int off = 16; off; off >>= 1)
        mx = fmaxf(mx, __shfl_xor_sync(0xffffffffu, mx, off));
    float e = (lane < OSZ) ? __expf(om - mx) : 0.f;
    float s = e;
#pragma unroll
    for (int off = 16; off; off >>= 1)
        s += __shfl_xor_sync(0xffffffffu, s, off);
    if (lane < OSZ)
        out[((size_t)b * OSZ + lane) * TLEN + t] = om - mx - __logf(s);
}

// ---------------------------------------------------------------------------
extern "C" void kernel_launch(void* const* d_in, const int* in_sizes, int n_in,
                              void* d_out, int out_size) {
    const float* x         = (const float*)d_in[0];
    const float* W_i2h     = (const float*)d_in[1];
    const float* b_i2h     = (const float*)d_in[2];
    const float* W_h2h     = (const float*)d_in[3];
    const float* b_h2h     = (const float*)d_in[4];
    const float* W_h2o     = (const float*)d_in[5];
    const float* b_h2o     = (const float*)d_in[6];
    const float* tau_adp_o = (const float*)d_in[8];
    const float* tau_m_h   = (const float*)d_in[9];
    const float* tau_m_o   = (const float*)d_in[10];
    const float* h0        = (const float*)d_in[11];
    const float* o0        = (const float*)d_in[12];
    float* out = (float*)d_out;

    static int inited = 0;
    if (!inited) {
        cudaFuncSetAttribute(scan_kernel,
                             cudaFuncAttributeMaxDynamicSharedMemorySize,
                             SCAN_SMEM_FLOATS * 4);
        inited = 1;
    }

    prep_kernel<<<(ISZ * HSZ + 255) / 256, 256>>>(W_i2h, W_h2h);

    gemm_kernel<<<GEMM_GRID, 256>>>(x, b_i2h, b_h2h);

    scan_kernel<<<BSZ, NTH, SCAN_SMEM_FLOATS * 4>>>(tau_m_h, h0);

    oin_kernel<<<BSZ * TLEN / (OIN_WARPS * OIN_TASKS), OIN_WARPS * 32>>>(W_h2o);

    orec_kernel<<<(BSZ * OSZ + 255) / 256, 256>>>(b_h2o, tau_adp_o, tau_m_o, o0);

    softmax_kernel<<<BSZ * TLEN / 8, 256>>>(out);
}

// round 14
// speedup vs baseline: 1.5018x; 1.0987x over previous
#include <cuda_runtime.h>
#include <math.h>
#include <math_constants.h>
#include <stdint.h>

#define BSZ  128
#define TLEN 500
#define ISZ  700
#define HSZ  256
#define OSZ  20
#define BJ0  0.01f

// Scratch. g_hpre layout: [b][t][n]
__device__ float    g_hpre[(size_t)BSZ * TLEN * HSZ];
__device__ float    g_wit[ISZ * HSZ];               // W_i2h^T [700][256]
__device__ float    g_wth[HSZ * HSZ];               // W_h2h^T [j][i]
__device__ unsigned g_ball[(size_t)BSZ * TLEN * 8]; // spike masks [b*T+t][8]
__device__ float    g_oin[(size_t)BSZ * TLEN * OSZ];
__device__ float    g_om [(size_t)BSZ * TLEN * OSZ];

// ---------------------------------------------------------------------------
__global__ void prep_kernel(const float* __restrict__ Wi,
                            const float* __restrict__ Wh) {
    int idx = blockIdx.x * blockDim.x + threadIdx.x;
    if (idx < ISZ * HSZ) {
        int k = idx / HSZ, n = idx % HSZ;
        g_wit[idx] = Wi[n * ISZ + k];
    }
    if (idx < HSZ * HSZ) {
        int j = idx / HSZ, i = idx % HSZ;
        g_wth[idx] = Wh[i * HSZ + j];
    }
}

// ---------------------------------------------------------------------------
// Persistent GEMM (R4 exact; bitwise-identical hpre)
// ---------------------------------------------------------------------------
#define FMA2(acc, a, b) \
    asm("fma.rn.f32x2 %0, %1, %2, %0;" : "+l"(acc) : "l"(a), "l"(b))

#define GEMM_TILES 1000
#define GEMM_GRID  296

__global__ void __launch_bounds__(256, 2) gemm_kernel(
    const float* __restrict__ A,
    const float* __restrict__ bi,
    const float* __restrict__ bh) {
    const int N = HSZ, K = ISZ;
    __shared__ __align__(16) float As[2][8][128];
    __shared__ __align__(16) float Bs[2][8][128];

    int tid = threadIdx.x;
    int tx = tid & 15, ty = tid >> 4;
    int arow  = tid >> 1,  acol4 = (tid & 1) * 4;
    int brow  = tid >> 5,  bcol4 = (tid & 31) * 4;

    for (int tile = blockIdx.x; tile < GEMM_TILES; tile += GEMM_GRID) {
        int bm = (tile >> 1) * 128;
        int bn = (tile & 1) * 128;
        const float* Aptr = A + (size_t)(bm + arow) * K;

        unsigned long long acc2[8][4];
#pragma unroll
        for (int i = 0; i < 8; i++)
#pragma unroll
            for (int j = 0; j < 4; j++) acc2[i][j] = 0ull;

        {
            float4 av = make_float4(0.f, 0.f, 0.f, 0.f);
            float4 bv = make_float4(0.f, 0.f, 0.f, 0.f);
            if (acol4 < K) av = *(const float4*)(Aptr + acol4);
            if (brow  < K) bv = *(const float4*)(g_wit + (size_t)brow * N + bn + bcol4);
            As[0][acol4 + 0][arow] = av.x;
            As[0][acol4 + 1][arow] = av.y;
            As[0][acol4 + 2][arow] = av.z;
            As[0][acol4 + 3][arow] = av.w;
            *(float4*)&Bs[0][brow][bcol4] = bv;
        }
        __syncthreads();

        int p = 0;
        for (int k0 = 0; k0 < K; k0 += 8) {
            bool more = (k0 + 8) < K;
            float4 av2 = make_float4(0.f, 0.f, 0.f, 0.f);
            float4 bv2 = make_float4(0.f, 0.f, 0.f, 0.f);
            if (more) {
                int ac = k0 + 8 + acol4;
                int bk = k0 + 8 + brow;
                if (ac < K) av2 = *(const float4*)(Aptr + ac);
                if (bk < K) bv2 = *(const float4*)(g_wit + (size_t)bk * N + bn + bcol4);
            }
#pragma unroll
            for (int kk = 0; kk < 8; kk++) {
                float4 a0 = *(const float4*)&As[p][kk][ty * 8];
                float4 a1 = *(const float4*)&As[p][kk][ty * 8 + 4];
                const unsigned long long* bp =
                    (const unsigned long long*)&Bs[p][kk][tx * 8];
                unsigned long long bb0 = bp[0], bb1 = bp[1], bb2 = bp[2], bb3 = bp[3];
                float af[8] = {a0.x, a0.y, a0.z, a0.w, a1.x, a1.y, a1.z, a1.w};
#pragma unroll
                for (int i = 0; i < 8; i++) {
                    unsigned long long aa;
                    unsigned ai = __float_as_uint(af[i]);
                    asm("mov.b64 %0, {%1, %1};" : "=l"(aa) : "r"(ai));
                    FMA2(acc2[i][0], aa, bb0);
                    FMA2(acc2[i][1], aa, bb1);
                    FMA2(acc2[i][2], aa, bb2);
                    FMA2(acc2[i][3], aa, bb3);
                }
            }
            if (more) {
                As[p ^ 1][acol4 + 0][arow] = av2.x;
                As[p ^ 1][acol4 + 1][arow] = av2.y;
                As[p ^ 1][acol4 + 2][arow] = av2.z;
                As[p ^ 1][acol4 + 3][arow] = av2.w;
                *(float4*)&Bs[p ^ 1][brow][bcol4] = bv2;
            }
            __syncthreads();
            p ^= 1;
        }

        float biasv[8];
#pragma unroll
        for (int j = 0; j < 8; j++) {
            int n = bn + tx * 8 + j;
            biasv[j] = bi[n] + bh[n];
        }
#pragma unroll
        for (int i = 0; i < 8; i++) {
            size_t m = (size_t)(bm + ty * 8 + i);
            float r[8];
#pragma unroll
            for (int j = 0; j < 4; j++) {
                unsigned lo, hi;
                asm("mov.b64 {%0, %1}, %2;" : "=r"(lo), "=r"(hi) : "l"(acc2[i][j]));
                r[2 * j]     = __uint_as_float(lo) + biasv[2 * j];
                r[2 * j + 1] = __uint_as_float(hi) + biasv[2 * j + 1];
            }
            float4 v0 = make_float4(r[0], r[1], r[2], r[3]);
            float4 v1 = make_float4(r[4], r[5], r[6], r[7]);
            *(float4*)(g_hpre + m * HSZ + bn + tx * 8)     = v0;
            *(float4*)(g_hpre + m * HSZ + bn + tx * 8 + 4) = v1;
        }
    }
}

// ---------------------------------------------------------------------------
// Shared helpers
// ---------------------------------------------------------------------------
#define TREE8(w0,w1,w2,w3,w4,w5,w6,w7) \
    (((w0 + w1) + (w2 + w3)) + ((w4 + w5) + (w6 + w7)))

// Warp-private scatter over 8 words (post-pass; ascending 0..255).
__device__ __forceinline__ int warp_scatter8(const unsigned w[8], int lane,
                                             int* __restrict__ seg) {
    int cnt = 0;
#pragma unroll
    for (int k2 = 0; k2 < 8; k2++) cnt += __popc(w[k2]);
    const int wi = lane >> 2;
    const int bitbase = (lane & 3) * 8;
    int pos = 0;
#pragma unroll
    for (int k2 = 0; k2 < 8; k2++)
        if (k2 < wi) pos += __popc(w[k2]);
    unsigned myw = w[wi];
    pos += __popc(myw & ((1u << bitbase) - 1u));
    unsigned byte = (myw >> bitbase) & 0xffu;
    int base_n = lane * 8;
#pragma unroll
    for (int k2 = 0; k2 < 8; k2++)
        if (byte & (1u << k2)) seg[pos++] = base_n + k2;
    __syncwarp();
    return cnt;
}

// Warp-private scatter over 4 words (scan lower half; ascending 0..127).
__device__ __forceinline__ int warp_scatter4(const unsigned w[4], int lane,
                                             int* __restrict__ seg) {
    int cnt = 0;
#pragma unroll
    for (int k2 = 0; k2 < 4; k2++) cnt += __popc(w[k2]);
    const int wi = lane >> 3;            // 0..3
    const int bitbase = (lane & 7) * 4;  // 0..28
    int pos = 0;
#pragma unroll
    for (int k2 = 0; k2 < 4; k2++)
        if (k2 < wi) pos += __popc(w[k2]);
    unsigned myw = w[wi];
    pos += __popc(myw & ((1u << bitbase) - 1u));
    unsigned nib = (myw >> bitbase) & 0xfu;
    int base_n = lane * 4;
#pragma unroll
    for (int k2 = 0; k2 < 4; k2++)
        if (nib & (1u << k2)) seg[pos++] = base_n + k2;
    __syncwarp();
    return cnt;
}

// 16-wide gather: same add ORDER as 8-wide (racc+=T1; racc+=T2).
__device__ __forceinline__ float gather_list16(const float* __restrict__ w,
                                               const int* __restrict__ lst,
                                               int cnt, int stride) {
    float racc = 0.f;
    int i = 0;
#pragma unroll 1
    for (; i + 16 <= cnt; i += 16) {
        int4 ja = *(const int4*)(lst + i);
        int4 jb = *(const int4*)(lst + i + 4);
        int4 jc = *(const int4*)(lst + i + 8);
        int4 jd = *(const int4*)(lst + i + 12);
        float w0 = w[ja.x * stride], w1 = w[ja.y * stride];
        float w2 = w[ja.z * stride], w3 = w[ja.w * stride];
        float w4 = w[jb.x * stride], w5 = w[jb.y * stride];
        float w6 = w[jb.z * stride], w7 = w[jb.w * stride];
        float x0 = w[jc.x * stride], x1 = w[jc.y * stride];
        float x2 = w[jc.z * stride], x3 = w[jc.w * stride];
        float x4 = w[jd.x * stride], x5 = w[jd.y * stride];
        float x6 = w[jd.z * stride], x7 = w[jd.w * stride];
        float t1 = TREE8(w0, w1, w2, w3, w4, w5, w6, w7);
        float t2 = TREE8(x0, x1, x2, x3, x4, x5, x6, x7);
        racc += t1;
        racc += t2;
    }
    if (i + 8 <= cnt) {
        int4 ja = *(const int4*)(lst + i);
        int4 jb = *(const int4*)(lst + i + 4);
        float w0 = w[ja.x * stride], w1 = w[ja.y * stride];
        float w2 = w[ja.z * stride], w3 = w[ja.w * stride];
        float w4 = w[jb.x * stride], w5 = w[jb.y * stride];
        float w6 = w[jb.z * stride], w7 = w[jb.w * stride];
        racc += TREE8(w0, w1, w2, w3, w4, w5, w6, w7);
        i += 8;
    }
#pragma unroll 1
    for (; i < cnt; ++i)
        racc += w[lst[i] * stride];
    return racc;
}

// ---------------------------------------------------------------------------
// Scan: ONE CTA per batch (no cluster!). 256 threads = 256 neurons.
// Lower weight half (j<128) in smem, sparse ballot-gather.
// Upper half (j>=128) in REGISTERS as 64 f32x2 pairs, dense FFMA2 against
// spike-float pairs (x*0 terms are exact no-ops). One __syncthreads/step.
// ---------------------------------------------------------------------------
#define NTH 256
#define SCAN_SMEM_FLOATS 34320   // 137,280 bytes

__global__ void __launch_bounds__(NTH, 1)
scan_kernel(const float* __restrict__ tau_m_h,
            const float* __restrict__ h0)
{
    extern __shared__ float smf[];
    float*    s_wt   = smf;                        // [128 j][256 i] 128 KB
    float*    s_spkf = smf + 32768;                // [2][256] spike floats
    int*      s_idx  = (int*)(smf + 33280);        // [8 warps][128]
    unsigned* s_bal  = (unsigned*)(smf + 34304);   // [2 slot][8]

    const int tid  = threadIdx.x;
    const int lane = tid & 31;
    const int wid  = tid >> 5;
    const int b    = blockIdx.x;

    // lower weight half -> smem (direct copy: g_wth rows j=0..127)
    for (int i = tid; i < 8192; i += NTH)
        ((float4*)s_wt)[i] = ((const float4*)g_wth)[i];

    // upper weight half -> registers, packed as f32x2 pairs
    unsigned long long w2[64];
#pragma unroll
    for (int k = 0; k < 64; k++) {
        float lo = g_wth[(size_t)(128 + 2 * k) * HSZ + tid];
        float hi = g_wth[(size_t)(129 + 2 * k) * HSZ + tid];
        asm("mov.b64 %0, {%1, %2};"
            : "=l"(w2[k])
            : "r"(__float_as_uint(lo)), "r"(__float_as_uint(hi)));
    }

    const float a_h      = expf(-1.f / tau_m_h[tid]);
    const float one_m_ah = 1.f - a_h;
    float h_mem = h0[(size_t)b * HSZ + tid];
    float spf   = h_mem;
    s_spkf[tid] = spf;                             // slot 0 = initial spikes
    __syncthreads();

    const float* hp = g_hpre + ((size_t)b * TLEN) * HSZ + tid;
    float pre = __ldcs(hp);
    int* myseg = s_idx + wid * 128;
    unsigned* gb = g_ball + ((size_t)b * TLEN) * 8 + wid;

#pragma unroll 1
    for (int t = 0; t < TLEN; ++t) {
        const int rs = t & 1;                      // read slot
        float racc;

        if (t == 0) {
            // exact j=0..255 sequential chain (bitwise = earlier rounds)
            const float* sp0 = s_spkf;             // slot 0
            racc = 0.f;
#pragma unroll 8
            for (int j = 0; j < 128; ++j)
                racc += s_wt[j * 256 + tid] * sp0[j];
#pragma unroll
            for (int k = 0; k < 64; ++k) {
                unsigned lo, hi;
                asm("mov.b64 {%0, %1}, %2;" : "=r"(lo), "=r"(hi) : "l"(w2[k]));
                racc += __uint_as_float(lo) * sp0[128 + 2 * k];
                racc += __uint_as_float(hi) * sp0[128 + 2 * k + 1];
            }
        } else {
            // sparse lower half
            const unsigned* wp = s_bal + rs * 8;
            unsigned w4[4] = {wp[0], wp[1], wp[2], wp[3]};
            int cnt = warp_scatter4(w4, lane, myseg);
            float rs_lo = gather_list16(s_wt + tid, myseg, cnt, 256);

            // dense register upper half: 64 FFMA2, 8 chains
            unsigned long long dacc[8];
#pragma unroll
            for (int c = 0; c < 8; c++) dacc[c] = 0ull;
            const ulonglong2* sp2 =
                (const ulonglong2*)(s_spkf + rs * 256 + 128);
#pragma unroll
            for (int m = 0; m < 32; m++) {
                ulonglong2 s2 = sp2[m];
                FMA2(dacc[(2 * m) & 7],     w2[2 * m],     s2.x);
                FMA2(dacc[(2 * m + 1) & 7], w2[2 * m + 1], s2.y);
            }
            float df[8];
#pragma unroll
            for (int c = 0; c < 8; c++) {
                unsigned lo, hi;
                asm("mov.b64 {%0, %1}, %2;" : "=r"(lo), "=r"(hi) : "l"(dacc[c]));
                df[c] = __uint_as_float(lo) + __uint_as_float(hi);
            }
            float rs_hi = TREE8(df[0], df[1], df[2], df[3],
                                df[4], df[5], df[6], df[7]);
            racc = rs_lo + rs_hi;
        }

        float acc = pre + racc;
        if (t + 1 < TLEN) pre = __ldcs(hp + (size_t)(t + 1) * HSZ);

        h_mem = h_mem * a_h + one_m_ah * acc - BJ0 * spf;
        int sp = (h_mem - BJ0) > 0.f;
        spf = sp ? 1.f : 0.f;
        unsigned bal = __ballot_sync(0xffffffffu, sp);

        const int ws = (t + 1) & 1;                // write slot
        if (lane == 0) {
            s_bal[ws * 8 + wid] = bal;
            __stcs(gb + (size_t)t * 8, bal);       // for output post-pass
        }
        s_spkf[ws * 256 + tid] = spf;
        __syncthreads();
    }
}

// ---------------------------------------------------------------------------
// Post-pass A (persistent): oin[b][t][o] = sum over spiking j of Wo^T[j][o].
// ---------------------------------------------------------------------------
#define OIN_WARPS 8
#define OIN_TASKS 16   // per warp

__global__ void __launch_bounds__(OIN_WARPS * 32) oin_kernel(
    const float* __restrict__ Wo) {
    __shared__ float s_woT[HSZ * OSZ];     // [j][o], 20 KB
    __shared__ int   s_list[OIN_WARPS][256];

    int tid = threadIdx.x, lane = tid & 31, wid = tid >> 5;
    for (int i = tid; i < OSZ * HSZ; i += OIN_WARPS * 32) {
        int o = i >> 8, j = i & 255;
        s_woT[j * OSZ + o] = Wo[i];
    }
    __syncthreads();

    int task0 = (blockIdx.x * OIN_WARPS + wid) * OIN_TASKS;
#pragma unroll 1
    for (int it = 0; it < OIN_TASKS; ++it) {
        int task = task0 + it;             // = b*TLEN + t, < 64000
        const unsigned* gb = g_ball + (size_t)task * 8;
        unsigned w[8];
#pragma unroll
        for (int k = 0; k < 8; k++) w[k] = gb[k];
        int cnt = warp_scatter8(w, lane, s_list[wid]);
        if (lane < OSZ) {
            float v = gather_list16(s_woT + lane, s_list[wid], cnt, OSZ);
            g_oin[(size_t)task * OSZ + lane] = v;
        }
        __syncwarp();
    }
}

// ---------------------------------------------------------------------------
// Post-pass B: per-(b,o) ALIF recurrence over t (2560 threads)
// ---------------------------------------------------------------------------
__global__ void __launch_bounds__(256) orec_kernel(
    const float* __restrict__ bo_bias,
    const float* __restrict__ tau_adp_o,
    const float* __restrict__ tau_m_o,
    const float* __restrict__ o0) {
    int gt = blockIdx.x * blockDim.x + threadIdx.x;
    if (gt >= BSZ * OSZ) return;
    int b = gt / OSZ, o = gt % OSZ;

    const float alpha = expf(-1.f / tau_m_o[o]);
    const float ro    = expf(-1.f / tau_adp_o[o]);
    const float oma   = 1.f - alpha;
    const float omr   = 1.f - ro;
    const float bias  = bo_bias[o];

    float om  = o0[(size_t)b * OSZ + o];
    float osp = om;
    float bo  = BJ0;

    const float* oi = g_oin + (size_t)b * TLEN * OSZ + o;
    float*       od = g_om  + (size_t)b * TLEN * OSZ + o;
    float pre = oi[0];
#pragma unroll 1
    for (int t = 0; t < TLEN; ++t) {
        float oin = bias + pre;
        if (t + 1 < TLEN) pre = oi[(size_t)(t + 1) * OSZ];
        bo = ro * bo + omr * osp;
        float Bo = BJ0 + 1.8f * bo;
        om = om * alpha + oma * oin - Bo * osp;
        osp = ((om - Bo) > 0.f) ? 1.f : 0.f;
        od[(size_t)t * OSZ] = om;
    }
}

// ---------------------------------------------------------------------------
// Post-pass C: log-softmax per (b,t), one warp each
// ---------------------------------------------------------------------------
__global__ void __launch_bounds__(256) softmax_kernel(float* __restrict__ out) {
    int lane = threadIdx.x & 31, wid = threadIdx.x >> 5;
    int task = blockIdx.x * 8 + wid;       // = b*TLEN + t
    int b = task / TLEN, t = task % TLEN;

    float om = (lane < OSZ) ? g_om[(size_t)task * OSZ + lane] : -CUDART_INF_F;
    float mx = om;
#pragma unroll
    for (int off = 16; off; off >>= 1)
        mx = fmaxf(mx, __shfl_xor_sync(0xffffffffu, mx, off));
    float e = (lane < OSZ) ? __expf(om - mx) : 0.f;
    float s = e;
#pragma unroll
    for (int off = 16; off; off >>= 1)
        s += __shfl_xor_sync(0xffffffffu, s, off);
    if (lane < OSZ)
        out[((size_t)b * OSZ + lane) * TLEN + t] = om - mx - __logf(s);
}

// ---------------------------------------------------------------------------
extern "C" void kernel_launch(void* const* d_in, const int* in_sizes, int n_in,
                              void* d_out, int out_size) {
    const float* x         = (const float*)d_in[0];
    const float* W_i2h     = (const float*)d_in[1];
    const float* b_i2h     = (const float*)d_in[2];
    const float* W_h2h     = (const float*)d_in[3];
    const float* b_h2h     = (const float*)d_in[4];
    const float* W_h2o     = (const float*)d_in[5];
    const float* b_h2o     = (const float*)d_in[6];
    const float* tau_adp_o = (const float*)d_in[8];
    const float* tau_m_h   = (const float*)d_in[9];
    const float* tau_m_o   = (const float*)d_in[10];
    const float* h0        = (const float*)d_in[11];
    const float* o0        = (const float*)d_in[12];
    float* out = (float*)d_out;

    static int inited = 0;
    if (!inited) {
        cudaFuncSetAttribute(scan_kernel,
                             cudaFuncAttributeMaxDynamicSharedMemorySize,
                             SCAN_SMEM_FLOATS * 4);
        inited = 1;
    }

    prep_kernel<<<(ISZ * HSZ + 255) / 256, 256>>>(W_i2h, W_h2h);

    gemm_kernel<<<GEMM_GRID, 256>>>(x, b_i2h, b_h2h);

    scan_kernel<<<BSZ, NTH, SCAN_SMEM_FLOATS * 4>>>(tau_m_h, h0);

    oin_kernel<<<BSZ * TLEN / (OIN_WARPS * OIN_TASKS), OIN_WARPS * 32>>>(W_h2o);

    orec_kernel<<<(BSZ * OSZ + 255) / 256, 256>>>(b_h2o, tau_adp_o, tau_m_o, o0);

    softmax_kernel<<<BSZ * TLEN / 8, 256>>>(out);
}